// round 4
// baseline (speedup 1.0000x reference)
#include <cuda_runtime.h>

#define BB 8192
#define TT 2048
#define NTHREADS 256   // 8 warps/block -> 2 warps per SMSP (latency hiding partner)
#define NBLOCKS (BB / NTHREADS)   // 32 blocks -> 32 SMs, wave-1 spread
#define CHUNK 8        // timesteps per prefetch chunk (4 float4 per thread)

typedef unsigned long long u64;

__device__ __forceinline__ float tanh_ap(float x) {
    float y;
    asm("tanh.approx.f32 %0, %1;" : "=f"(y) : "f"(x));
    return y;
}
__device__ __forceinline__ u64 pk(float a, float b) {
    u64 r;
    asm("mov.b64 %0, {%1, %2};" : "=l"(r) : "f"(a), "f"(b));
    return r;
}
__device__ __forceinline__ void upk(float& a, float& b, u64 p) {
    asm("mov.b64 {%0, %1}, %2;" : "=f"(a), "=f"(b) : "l"(p));
}
// packed dual fp32 fma (FFMA2) — IEEE fma per lane, halves FMA issue count
__device__ __forceinline__ u64 ffma2(u64 a, u64 b, u64 c) {
    u64 r;
    asm("fma.rn.f32x2 %0, %1, %2, %3;" : "=l"(r) : "l"(a), "l"(b), "l"(c));
    return r;
}

// One thread = one batch element (chain). 2 warps/SMSP so the two warps
// cover each other's dependency-chain stalls; MUFU (10 tanh/step @ rt 8)
// becomes the binding pipe at ~160 cyc per SMSP per step.
__global__ void __launch_bounds__(NTHREADS, 1)
lstm_kernel(const float* __restrict__ x,
            const float* __restrict__ h0in,
            const float* __restrict__ c0in,
            const float* __restrict__ w_ih,
            const float* __restrict__ w_hh,
            const float* __restrict__ b_ih,
            const float* __restrict__ b_hh,
            float* __restrict__ out)
{
    const int b = blockIdx.x * NTHREADS + threadIdx.x;

    // Gate rows (torch order): [0,1]=i [2,3]=f [4,5]=g [6,7]=o.
    // sigma(z) = 0.5*tanh(0.5 z)+0.5 with the 0.5 folded into weights/bias.
    // Gate pairs p: z[2p], z[2p+1] packed in one f32x2 lane-pair.
    u64 WI0[4], WI1[4], WH0[4], WH1[4], BS[4];
#pragma unroll
    for (int p = 0; p < 4; p++) {
        const float s = (p == 2) ? 1.0f : 0.5f;   // pair 2 = g gates (tanh, unscaled)
        const int k0 = 2 * p, k1 = 2 * p + 1;
        WI0[p] = pk(s * __ldg(&w_ih[2*k0+0]), s * __ldg(&w_ih[2*k1+0]));
        WI1[p] = pk(s * __ldg(&w_ih[2*k0+1]), s * __ldg(&w_ih[2*k1+1]));
        WH0[p] = pk(s * __ldg(&w_hh[2*k0+0]), s * __ldg(&w_hh[2*k1+0]));
        WH1[p] = pk(s * __ldg(&w_hh[2*k0+1]), s * __ldg(&w_hh[2*k1+1]));
        BS[p]  = pk(s * (__ldg(&b_ih[k0]) + __ldg(&b_hh[k0])),
                    s * (__ldg(&b_ih[k1]) + __ldg(&b_hh[k1])));
    }

    float h_0 = h0in[2*b+0], h_1 = h0in[2*b+1];
    float c_0 = c0in[2*b+0], c_1 = c0in[2*b+1];
    float hc0 = 0.5f * c_0,  hc1 = 0.5f * c_1;   // running 0.5*c (off critical path)

    // x row: contiguous T*D = 4096 floats = 16 KB per thread.
    const float4* __restrict__ xr =
        reinterpret_cast<const float4*>(x) + (size_t)b * (TT * 2 / 4);

    // CHUNK timesteps = CHUNK/2 float4 per thread; double-buffered prefetch.
    float4 buf[2][CHUNK / 2];
#pragma unroll
    for (int q = 0; q < CHUNK / 2; q++) buf[0][q] = __ldg(&xr[q]);

#pragma unroll 1
    for (int ch = 0; ch < TT / CHUNK; ch++) {
        const int nb = (ch + 1) & 1;
        if (ch + 1 < TT / CHUNK) {
#pragma unroll
            for (int q = 0; q < CHUNK / 2; q++)
                buf[nb][q] = __ldg(&xr[(ch + 1) * (CHUNK / 2) + q]);
        }
#pragma unroll
        for (int s2 = 0; s2 < CHUNK / 2; s2++) {
            const float4 v = buf[ch & 1][s2];
#pragma unroll
            for (int half = 0; half < 2; half++) {
                const float x0 = half ? v.z : v.x;
                const float x1 = half ? v.w : v.y;

                // x/bias partial — NO h dependency: hoistable across steps,
                // fully off the recurrence critical path.
                const u64 X0 = pk(x0, x0), X1 = pk(x1, x1);
                u64 P[4];
#pragma unroll
                for (int p = 0; p < 4; p++) {
                    u64 t = ffma2(X1, WI1[p], BS[p]);
                    P[p] = ffma2(X0, WI0[p], t);
                }

                // h-dependent tail: pack + 2 packed fma deep from h.
                const u64 H0 = pk(h_0, h_0), H1 = pk(h_1, h_1);
#pragma unroll
                for (int p = 0; p < 4; p++) {
                    P[p] = ffma2(H1, WH1[p], P[p]);
                    P[p] = ffma2(H0, WH0[p], P[p]);
                }

                float z0, z1, z2, z3, z4, z5, z6, z7;
                upk(z0, z1, P[0]);
                upk(z2, z3, P[1]);
                upk(z4, z5, P[2]);
                upk(z6, z7, P[3]);

                const float ti0 = tanh_ap(z0), ti1 = tanh_ap(z1);
                const float tf0 = tanh_ap(z2), tf1 = tanh_ap(z3);
                const float tg0 = tanh_ap(z4), tg1 = tanh_ap(z5);
                const float to0 = tanh_ap(z6), to1 = tanh_ap(z7);

                const float si0 = fmaf(0.5f, ti0, 0.5f);
                const float si1 = fmaf(0.5f, ti1, 0.5f);
                const float so0 = fmaf(0.5f, to0, 0.5f);
                const float so1 = fmaf(0.5f, to1, 0.5f);

                // c' = (0.5c)*t_f + (0.5c + sigma(i)*t_g): one fma after tanh(f)
                const float q0 = fmaf(si0, tg0, hc0);
                const float q1 = fmaf(si1, tg1, hc1);
                c_0 = fmaf(hc0, tf0, q0);
                c_1 = fmaf(hc1, tf1, q1);

                const float tc0 = tanh_ap(c_0);
                const float tc1 = tanh_ap(c_1);
                h_0 = so0 * tc0;
                h_1 = so1 * tc1;
                hc0 = 0.5f * c_0;
                hc1 = 0.5f * c_1;
            }
        }
    }

    out[2*b+0] = c_0;
    out[2*b+1] = c_1;
}

extern "C" void kernel_launch(void* const* d_in, const int* in_sizes, int n_in,
                              void* d_out, int out_size) {
    const float* x    = (const float*)d_in[0];
    const float* h0   = (const float*)d_in[1];
    const float* c0   = (const float*)d_in[2];
    const float* w_ih = (const float*)d_in[3];
    const float* w_hh = (const float*)d_in[4];
    const float* b_ih = (const float*)d_in[5];
    const float* b_hh = (const float*)d_in[6];
    lstm_kernel<<<NBLOCKS, NTHREADS>>>(x, h0, c0, w_ih, w_hh, b_ih, b_hh,
                                       (float*)d_out);
}

// round 5
// speedup vs baseline: 1.4765x; 1.4765x over previous
#include <cuda_runtime.h>

#define BB 8192
#define TT 2048
#define NTHREADS 128           // 4 warps/block -> SMSP 0..3, 1 warp each
#define NBLOCKS  128           // 512 warps total; 16 chains/warp * 512 = 8192
#define CHUNK 8                // timesteps per prefetch chunk (4 float4 per lane)

__device__ __forceinline__ float tanh_ap(float x) {
    float y;
    asm("tanh.approx.f32 %0, %1;" : "=f"(y) : "f"(x));
    return y;
}

// Lane pair (2j, 2j+1) cooperates on one chain: lane parity u owns hidden
// unit u (its 4 gate rows, c_u, h_u). Per-warp MUFU instr per step: 5
// (i,f,g,o,tanh_c) instead of 10 -> 512 warps spread over 512 SMSPs, MUFU
// floor 80 cyc/step/SMSP. h exchange via 2x shfl.idx per step.
__global__ void __launch_bounds__(NTHREADS, 1)
lstm_kernel(const float* __restrict__ x,
            const float* __restrict__ h0in,
            const float* __restrict__ c0in,
            const float* __restrict__ w_ih,
            const float* __restrict__ w_hh,
            const float* __restrict__ b_ih,
            const float* __restrict__ b_hh,
            float* __restrict__ out)
{
    const int tid  = blockIdx.x * NTHREADS + threadIdx.x;
    const int lane = threadIdx.x & 31;
    const int pair = tid >> 1;          // chain (batch element) index
    const int u    = tid & 1;           // hidden unit owned by this lane

    // Gate rows (torch order): i=0+u, f=2+u, g=4+u, o=6+u.
    // sigma(z) = 0.5*tanh(0.5 z) + 0.5 with the 0.5 folded into weights/bias
    // for i,f,o (q=0,1,3); g (q=2) stays unscaled tanh.
    // w*0/w*1 multiply h_0/h_1 (global unit order), preserving R0's exact
    // fma sequence -> bitwise-identical results.
    float wi0[4], wi1[4], wh0[4], wh1[4], bs[4];   // q: 0=i,1=f,2=g,3=o
#pragma unroll
    for (int q = 0; q < 4; q++) {
        const int row = 2 * q + u;
        const float s = (q == 2) ? 1.0f : 0.5f;
        wi0[q] = s * __ldg(&w_ih[2*row+0]);
        wi1[q] = s * __ldg(&w_ih[2*row+1]);
        wh0[q] = s * __ldg(&w_hh[2*row+0]);
        wh1[q] = s * __ldg(&w_hh[2*row+1]);
        bs[q]  = s * (__ldg(&b_ih[row]) + __ldg(&b_hh[row]));
    }

    float h_own = h0in[2*pair + u];
    float c     = c0in[2*pair + u];
    float hc    = 0.5f * c;             // running 0.5*c, off the critical path

    // x row for this chain: contiguous T*D = 4096 floats; float4 = 2 steps.
    // Both lanes of the pair load the same addresses (same 16B line).
    const float4* __restrict__ xr =
        reinterpret_cast<const float4*>(x) + (size_t)pair * (TT * 2 / 4);

    float4 buf[2][CHUNK / 2];
#pragma unroll
    for (int q = 0; q < CHUNK / 2; q++) buf[0][q] = __ldg(&xr[q]);

    const int lane_e = lane & ~1;       // even lane of the pair (owns h0)
    const int lane_o = lane |  1;       // odd  lane of the pair (owns h1)

#pragma unroll 1
    for (int ch = 0; ch < TT / CHUNK; ch++) {
        const int nb = (ch + 1) & 1;
        if (ch + 1 < TT / CHUNK) {
#pragma unroll
            for (int q = 0; q < CHUNK / 2; q++)
                buf[nb][q] = __ldg(&xr[(ch + 1) * (CHUNK / 2) + q]);
        }
#pragma unroll
        for (int s2 = 0; s2 < CHUNK / 2; s2++) {
            const float4 v = buf[ch & 1][s2];
#pragma unroll
            for (int half = 0; half < 2; half++) {
                const float x0 = half ? v.z : v.x;
                const float x1 = half ? v.w : v.y;

                // Exchange hidden state: both lanes need (h0, h1) in global
                // unit order (keeps the R0 fma rounding order intact).
                const float h_0 = __shfl_sync(0xffffffffu, h_own, lane_e);
                const float h_1 = __shfl_sync(0xffffffffu, h_own, lane_o);

                // z per gate: x/bias part first (hoistable, no h dep),
                // then h_1, then h_0 — exactly R0's order.
                float z[4];
#pragma unroll
                for (int q = 0; q < 4; q++) {
                    float t = fmaf(x1, wi1[q], bs[q]);
                    t = fmaf(x0, wi0[q], t);
                    t = fmaf(h_1, wh1[q], t);
                    t = fmaf(h_0, wh0[q], t);
                    z[q] = t;
                }

                // MUFU order: i, f, g (c-path) -> tanh(c) -> o fills the pipe.
                const float ti = tanh_ap(z[0]);
                const float tf = tanh_ap(z[1]);
                const float tg = tanh_ap(z[2]);
                const float to = tanh_ap(z[3]);

                const float si = fmaf(0.5f, ti, 0.5f);

                // c' = (0.5c)*t_f + (0.5c + sigma(i)*t_g)
                const float q0 = fmaf(si, tg, hc);
                c = fmaf(hc, tf, q0);

                const float tc = tanh_ap(c);
                const float so = fmaf(0.5f, to, 0.5f);
                h_own = so * tc;
                hc = 0.5f * c;
            }
        }
    }

    out[2*pair + u] = c;
}

extern "C" void kernel_launch(void* const* d_in, const int* in_sizes, int n_in,
                              void* d_out, int out_size) {
    const float* x    = (const float*)d_in[0];
    const float* h0   = (const float*)d_in[1];
    const float* c0   = (const float*)d_in[2];
    const float* w_ih = (const float*)d_in[3];
    const float* w_hh = (const float*)d_in[4];
    const float* b_ih = (const float*)d_in[5];
    const float* b_hh = (const float*)d_in[6];
    lstm_kernel<<<NBLOCKS, NTHREADS>>>(x, h0, c0, w_ih, w_hh, b_ih, b_hh,
                                       (float*)d_out);
}